// round 4
// baseline (speedup 1.0000x reference)
#include <cuda_runtime.h>
#include <cuda_bf16.h>

#define NFEAT  6
#define D      256
#define NPAIRS 15
#define BM     32
#define TPB    256

// triu_indices(6, k=1) pair order
__device__ __constant__ int cPI[NPAIRS] = {0,0,0,0,0,1,1,1,1,2,2,2,3,3,4};
__device__ __constant__ int cPJ[NPAIRS] = {1,2,3,4,5,2,3,4,5,3,4,5,4,5,5};

// Copy 8192 contiguous floats (32 KB) gmem -> smem. 256 threads, 8 float4 each.
__device__ __forceinline__ void copy8k(float* __restrict__ dst,
                                       const float* __restrict__ src,
                                       int tid)
{
    const float4* s = (const float4*)src;
    float4*       d = (float4*)dst;
#pragma unroll
    for (int r = 0; r < 8; r++)
        d[tid + r * TPB] = s[tid + r * TPB];
}

// acc[4][8] += A[mr0..mr0+3][kbase..kbase+31] * Wc[0..31][n0..n0+7]
// A: [BM][D] row-major tile in smem (A reads are warp-broadcast: warp has fixed mr0)
// Wc: [32][D] row-major chunk in smem (contiguous reads across warp)
__device__ __forceinline__ void mma_chunk(const float* __restrict__ A, int kbase,
                                          const float* __restrict__ Wc,
                                          float acc[4][8], int mr0, int n0)
{
#pragma unroll
    for (int kk = 0; kk < 32; kk += 4) {
        float a[4][4];
#pragma unroll
        for (int i = 0; i < 4; i++) {
            float4 t = *(const float4*)(A + (mr0 + i) * D + kbase + kk);
            a[i][0] = t.x; a[i][1] = t.y; a[i][2] = t.z; a[i][3] = t.w;
        }
#pragma unroll
        for (int kj = 0; kj < 4; kj++) {
            float4 b0 = *(const float4*)(Wc + (kk + kj) * D + n0);
            float4 b1 = *(const float4*)(Wc + (kk + kj) * D + n0 + 4);
            float bb[8] = {b0.x, b0.y, b0.z, b0.w, b1.x, b1.y, b1.z, b1.w};
#pragma unroll
            for (int i = 0; i < 4; i++)
#pragma unroll
                for (int j = 0; j < 8; j++)
                    acc[i][j] = fmaf(a[i][kj], bb[j], acc[i][j]);
        }
    }
}

__global__ void __launch_bounds__(TPB, 2)
cblock_kernel(const float* __restrict__ features,  // [6][M][256]
              const float* __restrict__ W_pair,    // [15][512][256]
              const float* __restrict__ b_pair,    // [15][256]
              const float* __restrict__ W_final,   // [3840][256]
              const float* __restrict__ b_final,   // [256]
              const int*   __restrict__ NAS,       // [6]
              float*       __restrict__ out,       // [M][256]
              int M)
{
    extern __shared__ float smem[];
    float* sA = smem;                 // 32 x 256  (feature tile)
    float* sW = smem + BM * D;        // 32 x 256  (weight K-chunk)
    float* sH = smem + 2 * BM * D;    // 32 x 256  (tanh activations)
    __shared__ float sMask[NPAIRS];
    __shared__ int   sNas[NFEAT];

    const int tid = threadIdx.x;
    const int tn  = tid & 31;         // 32 groups along N
    const int tm  = tid >> 5;         // 8 groups along M (warp id -> broadcast A)
    const int n0  = tn * 8;
    const int mr0 = tm * 4;
    const size_t m0 = (size_t)blockIdx.x * BM;

    if (tid < NFEAT) { int v = NAS[tid]; if (tid < 2) v = 1; sNas[tid] = v; }
    __syncthreads();
    if (tid < NPAIRS) sMask[tid] = (float)(sNas[cPI[tid]] * sNas[cPJ[tid]]);
    __syncthreads();

    // out accumulator, init with b_final (broadcast over tokens)
    float oacc[4][8];
    {
        float4 f0 = *(const float4*)(b_final + n0);
        float4 f1 = *(const float4*)(b_final + n0 + 4);
#pragma unroll
        for (int i = 0; i < 4; i++) {
            oacc[i][0] = f0.x; oacc[i][1] = f0.y; oacc[i][2] = f0.z; oacc[i][3] = f0.w;
            oacc[i][4] = f1.x; oacc[i][5] = f1.y; oacc[i][6] = f1.z; oacc[i][7] = f1.w;
        }
    }

#pragma unroll 1
    for (int p = 0; p < NPAIRS; p++) {
        if (sMask[p] == 0.0f) continue;   // exact: masked pair contributes zero

        // h accumulator, init with b_pair[p]
        float hacc[4][8];
        {
            float4 b0 = *(const float4*)(b_pair + p * D + n0);
            float4 b1 = *(const float4*)(b_pair + p * D + n0 + 4);
#pragma unroll
            for (int i = 0; i < 4; i++) {
                hacc[i][0] = b0.x; hacc[i][1] = b0.y; hacc[i][2] = b0.z; hacc[i][3] = b0.w;
                hacc[i][4] = b1.x; hacc[i][5] = b1.y; hacc[i][6] = b1.z; hacc[i][7] = b1.w;
            }
        }

        // Stage 1: hacc += f_i @ W_top + f_j @ W_bot
#pragma unroll 1
        for (int half = 0; half < 2; half++) {
            const int f = half ? cPJ[p] : cPI[p];
            const float* ftile = features + ((size_t)f * M + m0) * D;
            const float* wbase = W_pair + ((size_t)p * 2 * D + (size_t)half * D) * D;

            __syncthreads();              // protect sA/sW reuse
            copy8k(sA, ftile, tid);
#pragma unroll 1
            for (int kc = 0; kc < 8; kc++) {
                if (kc) __syncthreads();
                copy8k(sW, wbase + (size_t)kc * 32 * D, tid);
                __syncthreads();
                mma_chunk(sA, kc * 32, sW, hacc, mr0, n0);
            }
        }

        // tanh -> sH  (mask is 1 here; 0-mask pairs were skipped exactly)
#pragma unroll
        for (int i = 0; i < 4; i++) {
            float4 v0, v1;
            v0.x = tanhf(hacc[i][0]); v0.y = tanhf(hacc[i][1]);
            v0.z = tanhf(hacc[i][2]); v0.w = tanhf(hacc[i][3]);
            v1.x = tanhf(hacc[i][4]); v1.y = tanhf(hacc[i][5]);
            v1.z = tanhf(hacc[i][6]); v1.w = tanhf(hacc[i][7]);
            *(float4*)(sH + (mr0 + i) * D + n0)     = v0;
            *(float4*)(sH + (mr0 + i) * D + n0 + 4) = v1;
        }

        // Stage 2: oacc += sH @ W_final[p*256:(p+1)*256, :]
        const float* wf = W_final + (size_t)p * D * D;
#pragma unroll 1
        for (int kc = 0; kc < 8; kc++) {
            __syncthreads();              // prev chunk compute done / sH writes visible
            copy8k(sW, wf + (size_t)kc * 32 * D, tid);
            __syncthreads();
            mma_chunk(sH, kc * 32, sW, oacc, mr0, n0);
        }
    }

    // epilogue: write output tile (coalesced float4)
    float* orow = out + m0 * D;
#pragma unroll
    for (int i = 0; i < 4; i++) {
        float4 v0, v1;
        v0.x = oacc[i][0]; v0.y = oacc[i][1]; v0.z = oacc[i][2]; v0.w = oacc[i][3];
        v1.x = oacc[i][4]; v1.y = oacc[i][5]; v1.z = oacc[i][6]; v1.w = oacc[i][7];
        *(float4*)(orow + (mr0 + i) * D + n0)     = v0;
        *(float4*)(orow + (mr0 + i) * D + n0 + 4) = v1;
    }
}

extern "C" void kernel_launch(void* const* d_in, const int* in_sizes, int n_in,
                              void* d_out, int out_size)
{
    const float* features = (const float*)d_in[0];
    const float* W_pair   = (const float*)d_in[1];
    const float* b_pair   = (const float*)d_in[2];
    const float* W_final  = (const float*)d_in[3];
    const float* b_final  = (const float*)d_in[4];
    const int*   NAS      = (const int*)d_in[5];
    float*       out      = (float*)d_out;

    const int M = in_sizes[0] / (NFEAT * D);      // 16384 tokens
    const int grid = M / BM;                      // 512 blocks
    const size_t smem_bytes = 3 * (size_t)BM * D * sizeof(float);   // 96 KB

    cudaFuncSetAttribute(cblock_kernel,
                         cudaFuncAttributeMaxDynamicSharedMemorySize,
                         (int)smem_bytes);
    cblock_kernel<<<grid, TPB, smem_bytes>>>(features, W_pair, b_pair,
                                             W_final, b_final, NAS, out, M);
}

// round 6
// speedup vs baseline: 1.5287x; 1.5287x over previous
#include <cuda_runtime.h>
#include <cuda_bf16.h>
#include <cstdint>

#define NFEAT  6
#define D      256
#define NPAIRS 15
#define BM     32
#define TPB    256
#define KC     16            // k-rows per pipelined chunk
#define NC     (D / KC)      // 16 chunks per 256-K GEMM

// triu_indices(6, k=1) pair order
__device__ __constant__ int cPI[NPAIRS] = {0,0,0,0,0,1,1,1,1,2,2,2,3,3,4};
__device__ __constant__ int cPJ[NPAIRS] = {1,2,3,4,5,2,3,4,5,3,4,5,4,5,5};

__device__ __forceinline__ void cp16(float* s, const float* g)
{
    unsigned int sa = (unsigned int)__cvta_generic_to_shared(s);
    asm volatile("cp.async.cg.shared.global [%0], [%1], 16;" :: "r"(sa), "l"(g));
}
#define CP_COMMIT() asm volatile("cp.async.commit_group;")
#define CP_WAIT0()  asm volatile("cp.async.wait_group 0;")

// One 256-K GEMM: acc[4][8] += Asm[32][256] @ wg[256][256], cp.async
// double-buffered over 16-row W chunks. Optionally loads Asm from ag (gmem)
// inside the first cp.async group.
// Column map: j in 0..3 -> col tn*4+j ; j in 4..7 -> col 128+tn*4+(j-4)
// (conflict-free LDS.128: warp's B read is 512B contiguous).
__device__ __forceinline__ void gemm_stage(const float* __restrict__ Asm,
                                           const float* __restrict__ wg,
                                           float*       __restrict__ sWbuf,
                                           float acc[4][8],
                                           int tid, int mr0, int tn,
                                           const float* __restrict__ ag)
{
    __syncthreads();                       // all warps done with sA/sW/sH users
    if (ag) {                              // stage A tile (32KB contiguous)
#pragma unroll
        for (int r = 0; r < 8; r++)
            cp16((float*)Asm + 4 * (tid + r * TPB), ag + 4 * (tid + r * TPB));
    }
#pragma unroll
    for (int r = 0; r < 4; r++)            // W chunk 0 -> buf0 (16KB)
        cp16(sWbuf + 4 * (tid + r * TPB), wg + 4 * (tid + r * TPB));
    CP_COMMIT();

#pragma unroll 1
    for (int kc = 0; kc < NC; kc++) {
        CP_WAIT0();
        __syncthreads();                   // chunk kc (and A) visible to all
        if (kc + 1 < NC) {                 // prefetch chunk kc+1, overlaps mma
            float*       nb = sWbuf + ((kc + 1) & 1) * (KC * D);
            const float* ng = wg + (size_t)(kc + 1) * KC * D;
#pragma unroll
            for (int r = 0; r < 4; r++)
                cp16(nb + 4 * (tid + r * TPB), ng + 4 * (tid + r * TPB));
            CP_COMMIT();
        }
        const float* Wc = sWbuf + (kc & 1) * (KC * D);
        const int kb = kc * KC;
#pragma unroll
        for (int kk = 0; kk < KC; kk += 4) {
            float a[4][4];
#pragma unroll
            for (int i = 0; i < 4; i++) {  // warp-broadcast A reads
                float4 t = *(const float4*)(Asm + (mr0 + i) * D + kb + kk);
                a[i][0] = t.x; a[i][1] = t.y; a[i][2] = t.z; a[i][3] = t.w;
            }
#pragma unroll
            for (int kj = 0; kj < 4; kj++) {
                float4 b0 = *(const float4*)(Wc + (kk + kj) * D + tn * 4);
                float4 b1 = *(const float4*)(Wc + (kk + kj) * D + 128 + tn * 4);
                float bb[8] = {b0.x, b0.y, b0.z, b0.w, b1.x, b1.y, b1.z, b1.w};
#pragma unroll
                for (int i = 0; i < 4; i++)
#pragma unroll
                    for (int j = 0; j < 8; j++)
                        acc[i][j] = fmaf(a[i][kj], bb[j], acc[i][j]);
            }
        }
    }
}

__global__ void __launch_bounds__(TPB, 2)
cblock_kernel(const float* __restrict__ features,  // [6][M][256]
              const float* __restrict__ W_pair,    // [15][512][256]
              const float* __restrict__ b_pair,    // [15][256]
              const float* __restrict__ W_final,   // [3840][256]
              const float* __restrict__ b_final,   // [256]
              const int*   __restrict__ NAS,       // [6]
              float*       __restrict__ out,       // [M][256]
              int M)
{
    extern __shared__ float smem[];
    float* sA = smem;                     // 32 x 256   (feature tile)
    float* sW = smem + BM * D;            // 2 x 16x256 (double-buffered W chunk)
    float* sH = smem + 2 * BM * D;        // 32 x 256   (tanh activations)
    __shared__ float sMask[NPAIRS];
    __shared__ int   sNas[NFEAT];

    const int tid = threadIdx.x;
    const int tn  = tid & 31;
    const int tm  = tid >> 5;             // warp id -> fixed m group (A broadcast)
    const int mr0 = tm * 4;
    const int c0  = tn * 4;               // first column group
    const int c1  = 128 + tn * 4;         // second column group
    const size_t m0 = (size_t)blockIdx.x * BM;

    if (tid < NFEAT) { int v = NAS[tid]; if (tid < 2) v = 1; sNas[tid] = v; }
    __syncthreads();
    if (tid < NPAIRS) sMask[tid] = (float)(sNas[cPI[tid]] * sNas[cPJ[tid]]);
    __syncthreads();

    // out accumulator, init with b_final
    float oacc[4][8];
    {
        float4 f0 = *(const float4*)(b_final + c0);
        float4 f1 = *(const float4*)(b_final + c1);
#pragma unroll
        for (int i = 0; i < 4; i++) {
            oacc[i][0] = f0.x; oacc[i][1] = f0.y; oacc[i][2] = f0.z; oacc[i][3] = f0.w;
            oacc[i][4] = f1.x; oacc[i][5] = f1.y; oacc[i][6] = f1.z; oacc[i][7] = f1.w;
        }
    }

#pragma unroll 1
    for (int p = 0; p < NPAIRS; p++) {
        if (sMask[p] == 0.0f) continue;   // exact: masked pair contributes zero

        // h accumulator, init with b_pair[p]
        float hacc[4][8];
        {
            float4 b0 = *(const float4*)(b_pair + p * D + c0);
            float4 b1 = *(const float4*)(b_pair + p * D + c1);
#pragma unroll
            for (int i = 0; i < 4; i++) {
                hacc[i][0] = b0.x; hacc[i][1] = b0.y; hacc[i][2] = b0.z; hacc[i][3] = b0.w;
                hacc[i][4] = b1.x; hacc[i][5] = b1.y; hacc[i][6] = b1.z; hacc[i][7] = b1.w;
            }
        }

        // Stage 1: hacc += f_i @ W_top  +  f_j @ W_bot
        {
            const int fi = cPI[p], fj = cPJ[p];
            gemm_stage(sA, W_pair + (size_t)p * 2 * D * D, sW, hacc,
                       tid, mr0, tn, features + ((size_t)fi * M + m0) * D);
            gemm_stage(sA, W_pair + ((size_t)p * 2 * D + D) * D, sW, hacc,
                       tid, mr0, tn, features + ((size_t)fj * M + m0) * D);
        }

        // tanh -> sH (each thread writes its own cells; stage2's internal
        // barriers order these writes before any read)
#pragma unroll
        for (int i = 0; i < 4; i++) {
            float4 v0, v1;
            v0.x = tanhf(hacc[i][0]); v0.y = tanhf(hacc[i][1]);
            v0.z = tanhf(hacc[i][2]); v0.w = tanhf(hacc[i][3]);
            v1.x = tanhf(hacc[i][4]); v1.y = tanhf(hacc[i][5]);
            v1.z = tanhf(hacc[i][6]); v1.w = tanhf(hacc[i][7]);
            *(float4*)(sH + (mr0 + i) * D + c0) = v0;
            *(float4*)(sH + (mr0 + i) * D + c1) = v1;
        }

        // Stage 2: oacc += sH @ W_final[p*256:(p+1)*256, :]
        gemm_stage(sH, W_final + (size_t)p * D * D, sW, oacc,
                   tid, mr0, tn, (const float*)0);
    }

    // epilogue: coalesced float4 stores
    float* orow = out + m0 * D;
#pragma unroll
    for (int i = 0; i < 4; i++) {
        float4 v0, v1;
        v0.x = oacc[i][0]; v0.y = oacc[i][1]; v0.z = oacc[i][2]; v0.w = oacc[i][3];
        v1.x = oacc[i][4]; v1.y = oacc[i][5]; v1.z = oacc[i][6]; v1.w = oacc[i][7];
        *(float4*)(orow + (mr0 + i) * D + c0) = v0;
        *(float4*)(orow + (mr0 + i) * D + c1) = v1;
    }
}

extern "C" void kernel_launch(void* const* d_in, const int* in_sizes, int n_in,
                              void* d_out, int out_size)
{
    const float* features = (const float*)d_in[0];
    const float* W_pair   = (const float*)d_in[1];
    const float* b_pair   = (const float*)d_in[2];
    const float* W_final  = (const float*)d_in[3];
    const float* b_final  = (const float*)d_in[4];
    const int*   NAS      = (const int*)d_in[5];
    float*       out      = (float*)d_out;

    const int M = in_sizes[0] / (NFEAT * D);      // 16384 tokens
    const int grid = M / BM;                      // 512 blocks
    const size_t smem_bytes = 3 * (size_t)BM * D * sizeof(float);   // 96 KB

    cudaFuncSetAttribute(cblock_kernel,
                         cudaFuncAttributeMaxDynamicSharedMemorySize,
                         (int)smem_bytes);
    cblock_kernel<<<grid, TPB, smem_bytes>>>(features, W_pair, b_pair,
                                             W_final, b_final, NAS, out, M);
}